// round 14
// baseline (speedup 1.0000x reference)
#include <cuda_runtime.h>
#include <cuda_bf16.h>
#include <math_constants.h>

#define N_TOKENS   8192
#define QUANT_DIM  8192
#define OUTPUT_DIM 1024
#define SEC_COLS   32                       // one full 128B line per sector
#define N_SECTORS  (QUANT_DIM / SEC_COLS)   // 256
#define SLICE_ROWS 64
#define N_SLICES   (OUTPUT_DIM / SLICE_ROWS)   // 16
#define N_GATHER   (N_SECTORS * N_SLICES)      // 4096
#define GRID_SIZE  (N_TOKENS + N_GATHER)       // 12288
#define LIST_CHUNK 512

// Scratch (__device__ globals, zero-init at load). Invariant: the last
// gather block of every run resets all counters to zero (fence-ordered
// after every reader), so each graph replay starts from a clean state.
__device__ int g_ticket;
__device__ int g_adone;
__device__ int g_gdone;
__device__ int g_cnt[N_SECTORS];
__device__ int g_list[(size_t)N_SECTORS * N_TOKENS];   // packed (row<<5)|off

// ---------------------------------------------------------------------------
// Single fused kernel with dynamic roles.
//  ticket <  N_TOKENS : streaming argmax of row `ticket` (jnp first-index
//                       tie-break), push (row,off) to its sector list,
//                       fence, bump g_adone.
//  ticket >= N_TOKENS : gather block (sec, slice): preload W slice into smem
//                       (overlaps the argmax stream), spin until
//                       g_adone == N_TOKENS, then emit every listed token's
//                       64-float chunk (conflict-free LDS + coalesced STG).
// Ticket-based roles guarantee liveness: a spinning block implies all argmax
// blocks already started, and argmax never waits on gather.
// ---------------------------------------------------------------------------
__global__ __launch_bounds__(256) void fused_quantizer_kernel(
    const float* __restrict__ x, const float* __restrict__ W,
    float* __restrict__ out)
{
    __shared__ float s_tile[SLICE_ROWS * 33];   // gather: stride-33 W slice
    __shared__ int   s_list[LIST_CHUNK];
    __shared__ float s_val[8];
    __shared__ int   s_idx[8];
    __shared__ int   s_ticket, s_cnt, s_last;

    const int tid  = threadIdx.x;
    const int lane = tid & 31;
    const int warp = tid >> 5;

    if (tid == 0) s_ticket = atomicAdd(&g_ticket, 1);
    __syncthreads();
    const int ticket = s_ticket;

    if (ticket < N_TOKENS) {
        // ================= argmax role =================
        const int row = ticket;
        const float4* __restrict__ xr =
            reinterpret_cast<const float4*>(x + (size_t)row * QUANT_DIM);

        float best = -CUDART_INF_F;
        int   bidx = 0;

        #pragma unroll
        for (int it = 0; it < 8; ++it) {
            const int i = tid + it * 256;
            const float4 v = __ldcs(&xr[i]);           // streaming read
            const float vm = fmaxf(fmaxf(v.x, v.y), fmaxf(v.z, v.w));
            if (vm > best) {                            // rare after warmup
                best = vm;
                const int base = i * 4;
                bidx = (v.x == vm) ? base
                     : (v.y == vm) ? base + 1
                     : (v.z == vm) ? base + 2
                     :               base + 3;          // first-equal wins
            }
        }

        #pragma unroll
        for (int off = 16; off > 0; off >>= 1) {
            float ov = __shfl_down_sync(0xFFFFFFFFu, best, off);
            int   oi = __shfl_down_sync(0xFFFFFFFFu, bidx, off);
            if (ov > best || (ov == best && oi < bidx)) { best = ov; bidx = oi; }
        }
        if (lane == 0) { s_val[warp] = best; s_idx[warp] = bidx; }
        __syncthreads();

        if (warp == 0) {
            best = (lane < 8) ? s_val[lane] : -CUDART_INF_F;
            bidx = (lane < 8) ? s_idx[lane] : 0x7FFFFFFF;
            #pragma unroll
            for (int off = 4; off > 0; off >>= 1) {
                float ov = __shfl_down_sync(0xFFFFFFFFu, best, off);
                int   oi = __shfl_down_sync(0xFFFFFFFFu, bidx, off);
                if (ov > best || (ov == best && oi < bidx)) { best = ov; bidx = oi; }
            }
            if (lane == 0) {
                const int sec  = bidx >> 5;
                const int slot = atomicAdd(&g_cnt[sec], 1);
                g_list[((size_t)sec << 13) + slot] = (row << 5) | (bidx & 31);
                __threadfence();                  // publish entry before adone
                atomicAdd(&g_adone, 1);
            }
        }
        return;
    }

    // ================= gather role =================
    const int gid   = ticket - N_TOKENS;       // 0..4095
    const int sec   = gid >> 4;                // 16 consecutive gids: 1 sector
    const int slice = gid & 15;

    // Preload W slice NOW (independent of argmax -> overlapped, free time).
    #pragma unroll
    for (int it = 0; it < 2; ++it) {
        const int s  = tid + it * 256;
        const int r  = s >> 3;                 // row in slice (0..63)
        const int k4 = s & 7;                  // float4 within row
        const float4 v = __ldcs(reinterpret_cast<const float4*>(
            W + (size_t)(slice * SLICE_ROWS + r) * QUANT_DIM
              + sec * SEC_COLS + k4 * 4));
        s_tile[r * 33 + k4 * 4 + 0] = v.x;
        s_tile[r * 33 + k4 * 4 + 1] = v.y;
        s_tile[r * 33 + k4 * 4 + 2] = v.z;
        s_tile[r * 33 + k4 * 4 + 3] = v.w;
    }

    // Wait for all argmax blocks (acquire pattern), then read the count.
    if (tid == 0) {
        while (atomicAdd(&g_adone, 0) != N_TOKENS) __nanosleep(200);
        __threadfence();                        // acquire: order list reads
        s_cnt = g_cnt[sec];
    }
    __syncthreads();                            // tile ready + cnt visible

    const int cnt   = s_cnt;
    const int q     = tid >> 6;                 // 4 tokens per iteration
    const int c_loc = tid & 63;

    for (int base = 0; base < cnt; base += LIST_CHUNK) {
        const int chunk = min(cnt - base, LIST_CHUNK);
        for (int j = tid; j < chunk; j += 256)
            s_list[j] = g_list[((size_t)sec << 13) + base + j];
        __syncthreads();

        for (int t = q; t < chunk; t += 4) {
            const int e     = s_list[t];
            const int token = e >> 5;
            const int off   = e & 31;
            const float val = s_tile[c_loc * 33 + off];       // conflict-free
            __stcs(&out[(size_t)token * OUTPUT_DIM
                        + slice * SLICE_ROWS + c_loc], val);  // 256B coalesced
        }
        __syncthreads();                        // s_list reuse guard
    }

    // Last gather block resets all counters for the next graph replay.
    if (tid == 0) {
        __threadfence();                        // order reads before arrival
        const int d = atomicAdd(&g_gdone, 1);
        s_last = (d == N_GATHER - 1);
    }
    __syncthreads();
    if (s_last) {
        for (int i = tid; i < N_SECTORS; i += 256) g_cnt[i] = 0;
        if (tid == 0) { g_adone = 0; g_gdone = 0; g_ticket = 0; }
    }
}

// ---------------------------------------------------------------------------
extern "C" void kernel_launch(void* const* d_in, const int* in_sizes, int n_in,
                              void* d_out, int out_size)
{
    const float* x = (const float*)d_in[0];   // [8192, 8192] fp32
    const float* W = (const float*)d_in[1];   // [1024, 8192] fp32
    float* out = (float*)d_out;               // [8192, 1024] fp32

    fused_quantizer_kernel<<<GRID_SIZE, 256>>>(x, W, out);
}

// round 15
// speedup vs baseline: 1.1008x; 1.1008x over previous
#include <cuda_runtime.h>
#include <cuda_bf16.h>
#include <math_constants.h>

#define N_TOKENS   8192
#define QUANT_DIM  8192
#define OUTPUT_DIM 1024
#define SEC_COLS   32                       // one full 128B line per sector
#define N_SECTORS  (QUANT_DIM / SEC_COLS)   // 256
#define SLICE_ROWS 256
#define N_SLICES   (OUTPUT_DIM / SLICE_ROWS)   // 4
#define LIST_CHUNK 256

// Scratch (__device__ globals, zero-init at load). Invariant: gather resets
// g_cnt/g_done each run (fence-ordered after all readers) -> every graph
// replay starts clean.
__device__ int g_cnt[N_SECTORS];
__device__ int g_done[N_SECTORS];
__device__ int g_list[(size_t)N_SECTORS * N_TOKENS];   // packed (row<<5)|off

// ---------------------------------------------------------------------------
// Primary: streaming argmax, one block per row (jnp first-index tie-break).
// Triggers PDL completion AT ENTRY: the secondary's pre-sync phase reads
// only W, so it may launch/preload while argmax still runs.
// ---------------------------------------------------------------------------
__global__ __launch_bounds__(256) void argmax_rows_kernel(
    const float* __restrict__ x)
{
#if __CUDA_ARCH__ >= 900
    cudaTriggerProgrammaticLaunchCompletion();
#endif
    const int row = blockIdx.x;
    const float4* __restrict__ xr =
        reinterpret_cast<const float4*>(x + (size_t)row * QUANT_DIM);

    float best = -CUDART_INF_F;
    int   bidx = 0;

    #pragma unroll
    for (int it = 0; it < 8; ++it) {
        const int i = threadIdx.x + it * 256;
        const float4 v = __ldcs(&xr[i]);           // streaming read
        const float vm = fmaxf(fmaxf(v.x, v.y), fmaxf(v.z, v.w));
        if (vm > best) {                            // rare after warmup
            best = vm;
            const int base = i * 4;
            bidx = (v.x == vm) ? base
                 : (v.y == vm) ? base + 1
                 : (v.z == vm) ? base + 2
                 :               base + 3;          // first-equal = first index
        }
    }

    #pragma unroll
    for (int off = 16; off > 0; off >>= 1) {
        float ov = __shfl_down_sync(0xFFFFFFFFu, best, off);
        int   oi = __shfl_down_sync(0xFFFFFFFFu, bidx, off);
        if (ov > best || (ov == best && oi < bidx)) { best = ov; bidx = oi; }
    }

    __shared__ float s_val[8];
    __shared__ int   s_idx[8];
    const int lane = threadIdx.x & 31;
    const int warp = threadIdx.x >> 5;
    if (lane == 0) { s_val[warp] = best; s_idx[warp] = bidx; }
    __syncthreads();

    if (warp == 0) {
        best = (lane < 8) ? s_val[lane] : -CUDART_INF_F;
        bidx = (lane < 8) ? s_idx[lane] : 0x7FFFFFFF;
        #pragma unroll
        for (int off = 4; off > 0; off >>= 1) {
            float ov = __shfl_down_sync(0xFFFFFFFFu, best, off);
            int   oi = __shfl_down_sync(0xFFFFFFFFu, bidx, off);
            if (ov > best || (ov == best && oi < bidx)) { best = ov; bidx = oi; }
        }
        if (lane == 0) {
            const int sec  = bidx >> 5;
            const int slot = atomicAdd(&g_cnt[sec], 1);
            g_list[((size_t)sec << 13) + slot] = (row << 5) | (bidx & 31);
        }
    }
}

// ---------------------------------------------------------------------------
// Secondary (PDL): block (sec, slice) PRELOADS its 256-row x 32-col W slice
// into smem BEFORE cudaGridDependencySynchronize() -- this overlaps the
// argmax tail. After the sync (primary complete + memory visible), it stages
// the sector's token list and emits each token's 256-float chunk:
// conflict-free LDS (stride 33) + 128B-coalesced streaming STG.
// Reset: per-sector done counter; fence orders each block's cnt-read before
// its arrival, so the 4th arrival may safely zero cnt/done for next replay.
// ---------------------------------------------------------------------------
__global__ __launch_bounds__(256) void sector_gather_kernel(
    const float* __restrict__ W, float* __restrict__ out)
{
    __shared__ float s_tile[SLICE_ROWS * 33];   // 33 KB, stride-33
    __shared__ int   s_list[LIST_CHUNK];
    __shared__ int   s_cnt;

    const int sec   = blockIdx.x;
    const int slice = blockIdx.y;
    const int tid   = threadIdx.x;

    // ---- pre-sync: preload W slice (reads only W; overlaps primary) ----
    #pragma unroll
    for (int it = 0; it < 8; ++it) {
        const int s  = tid + it * 256;          // 2048 float4 slots
        const int r  = s >> 3;                  // row in slice (0..255)
        const int k4 = s & 7;                   // float4 within 32-col row
        const float4 v = __ldcs(reinterpret_cast<const float4*>(
            W + (size_t)(slice * SLICE_ROWS + r) * QUANT_DIM
              + sec * SEC_COLS + k4 * 4));
        s_tile[r * 33 + k4 * 4 + 0] = v.x;
        s_tile[r * 33 + k4 * 4 + 1] = v.y;
        s_tile[r * 33 + k4 * 4 + 2] = v.z;
        s_tile[r * 33 + k4 * 4 + 3] = v.w;
    }

#if __CUDA_ARCH__ >= 900
    cudaGridDependencySynchronize();            // wait: primary done + visible
#endif

    if (tid == 0) {
        const int c = g_cnt[sec];
        s_cnt = c;
        __threadfence();                        // cnt-read before arrival
        const int d = atomicAdd(&g_done[sec], 1);
        if (d == N_SLICES - 1) { g_cnt[sec] = 0; g_done[sec] = 0; }
    }
    __syncthreads();                            // tile + cnt ready

    const int cnt = s_cnt;

    for (int base = 0; base < cnt; base += LIST_CHUNK) {
        const int chunk = min(cnt - base, LIST_CHUNK);
        if (tid < chunk)
            s_list[tid] = g_list[((size_t)sec << 13) + base + tid];
        __syncthreads();

        for (int t = 0; t < chunk; ++t) {
            const int e     = s_list[t];                 // smem broadcast
            const int token = e >> 5;
            const int off   = e & 31;
            const float val = s_tile[tid * 33 + off];    // conflict-free
            __stcs(&out[(size_t)token * OUTPUT_DIM
                        + slice * SLICE_ROWS + tid], val);  // coalesced
        }
        __syncthreads();                        // s_list reuse guard
    }
}

// ---------------------------------------------------------------------------
extern "C" void kernel_launch(void* const* d_in, const int* in_sizes, int n_in,
                              void* d_out, int out_size)
{
    const float* x = (const float*)d_in[0];   // [8192, 8192] fp32
    const float* W = (const float*)d_in[1];   // [1024, 8192] fp32
    float* out = (float*)d_out;               // [8192, 1024] fp32

    argmax_rows_kernel<<<N_TOKENS, 256>>>(x);

    // Secondary with programmatic dependent launch: may begin (and preload W)
    // while the primary's tail is still running.
    cudaLaunchConfig_t cfg = {};
    cfg.gridDim  = dim3(N_SECTORS, N_SLICES);
    cfg.blockDim = dim3(256);
    cfg.dynamicSmemBytes = 0;
    cfg.stream = 0;
    cudaLaunchAttribute attr[1];
    attr[0].id = cudaLaunchAttributeProgrammaticStreamSerialization;
    attr[0].val.programmaticStreamSerializationAllowed = 1;
    cfg.attrs = attr;
    cfg.numAttrs = 1;
    cudaLaunchKernelEx(&cfg, sector_gather_kernel, W, out);
}